// round 15
// baseline (speedup 1.0000x reference)
#include <cuda_runtime.h>
#include <cuda_fp16.h>
#include <math.h>
#include <stdint.h>

#define NTOK 4096
#define CDIM 1024
#define HDIM 4096
#define NEXP 8
#define NSLOT (NTOK * 2)

// GEMM geometry: block tile 256(M) x 128(N) x 64(K) fp16, 256 threads = 8 warps (4m x 2n, warp 64x64)
#define STAGE_BYTES 49152            // A 32KB + B 16KB
#define SMEM_BYTES  (3 * STAGE_BYTES)

// ---------------- static device scratch ----------------
__device__ int g_offsets[NEXP + 1];
__device__ __align__(16) int g_rtok[NSLOT];
__device__ int g_e1[NTOK], g_e2[NTOK];
__device__ int g_s1[NTOK], g_s2[NTOK];
__device__ float g_w1[NTOK], g_w2[NTOK];
__device__ __align__(256) __half g_x16[(size_t)NTOK * CDIM];          // 8 MiB
__device__ __align__(256) __half g_w1h[(size_t)NEXP * CDIM * HDIM];   // 64 MiB
__device__ __align__(256) __half g_w2h[(size_t)NEXP * HDIM * CDIM];   // 64 MiB
__device__ __align__(256) __half g_h[(size_t)NSLOT * HDIM];           // 64 MiB
__device__ __align__(256) float  g_y[(size_t)NSLOT * CDIM];           // 32 MiB

#define NX4  (NTOK * CDIM / 4)
#define NW4  (NEXP * CDIM * HDIM / 4)
#define NW4E (CDIM * HDIM / 4)

// ---------------- helpers ----------------
__device__ __forceinline__ uint32_t smem_u32(const void* p) {
    uint32_t a;
    asm("{ .reg .u64 t; cvta.to.shared.u64 t, %1; cvt.u32.u64 %0, t; }" : "=r"(a) : "l"(p));
    return a;
}
#define SWZ(o)    ((o) ^ ((((uint32_t)(o)) >> 3) & 0x70u))   // 128B rows
#define SWZ256(o) ((o) ^ ((((uint32_t)(o)) >> 4) & 0x70u))   // 256B rows

__device__ __forceinline__ void cp16(uint32_t dst, const void* src) {
    asm volatile("cp.async.cg.shared.global [%0], [%1], 16;" :: "r"(dst), "l"(src) : "memory");
}
__device__ __forceinline__ void ldsm4(uint32_t& r0, uint32_t& r1, uint32_t& r2, uint32_t& r3, uint32_t a) {
    asm volatile("ldmatrix.sync.aligned.m8n8.x4.shared.b16 {%0,%1,%2,%3}, [%4];"
                 : "=r"(r0), "=r"(r1), "=r"(r2), "=r"(r3) : "r"(a));
}
__device__ __forceinline__ void ldsm4t(uint32_t& r0, uint32_t& r1, uint32_t& r2, uint32_t& r3, uint32_t a) {
    asm volatile("ldmatrix.sync.aligned.m8n8.x4.trans.shared.b16 {%0,%1,%2,%3}, [%4];"
                 : "=r"(r0), "=r"(r1), "=r"(r2), "=r"(r3) : "r"(a));
}
__device__ __forceinline__ void mma_f16(float* c, const uint32_t* a, const uint32_t* b) {
    asm volatile(
        "mma.sync.aligned.m16n8k16.row.col.f32.f16.f16.f32 "
        "{%0,%1,%2,%3}, {%4,%5,%6,%7}, {%8,%9}, {%0,%1,%2,%3};"
        : "+f"(c[0]), "+f"(c[1]), "+f"(c[2]), "+f"(c[3])
        : "r"(a[0]), "r"(a[1]), "r"(a[2]), "r"(a[3]), "r"(b[0]), "r"(b[1]));
}
__device__ __forceinline__ uint32_t h2u(__half2 h) { return *(uint32_t*)&h; }
__device__ __forceinline__ float gelu_exact(float v) {
    return 0.5f * v * (1.0f + erff(v * 0.70710678118654752f));
}
__device__ __forceinline__ void cvt_slice(const float4* __restrict__ src, uint2* __restrict__ dst,
                                          int start, int count, int tid, int nthr) {
    for (int i = start + tid; i < start + count; i += nthr) {
        float4 v = src[i];
        uint2 o;
        o.x = h2u(__floats2half2_rn(v.x, v.y));
        o.y = h2u(__floats2half2_rn(v.z, v.w));
        dst[i] = o;
    }
}

// ---------------- gate + x/W1 cvt (512 blocks x 256 thr) — R12 proven ----------------
__global__ void k_gate(const float* __restrict__ x, const float* __restrict__ Wg,
                       const float* __restrict__ bg, const float* __restrict__ W1) {
    int warp = (blockIdx.x * blockDim.x + threadIdx.x) >> 5;
    int lane = threadIdx.x & 31;
    if (warp < NTOK) {
        const float* xr = x + (size_t)warp * CDIM;
        float acc[NEXP];
#pragma unroll
        for (int e = 0; e < NEXP; e++) acc[e] = 0.f;
        for (int k = lane; k < CDIM; k += 32) {
            float xv = xr[k];
            const float* wr = Wg + k * NEXP;
#pragma unroll
            for (int e = 0; e < NEXP; e++) acc[e] = fmaf(xv, wr[e], acc[e]);
        }
#pragma unroll
        for (int off = 16; off; off >>= 1)
#pragma unroll
            for (int e = 0; e < NEXP; e++)
                acc[e] += __shfl_xor_sync(0xffffffffu, acc[e], off);
        if (lane == 0) {
#pragma unroll
            for (int e = 0; e < NEXP; e++) acc[e] += bg[e];
            int b1i = 0; float b1v = acc[0];
#pragma unroll
            for (int e = 1; e < NEXP; e++) if (acc[e] > b1v) { b1v = acc[e]; b1i = e; }
            int b2i = -1; float b2v = -3.0e38f;
#pragma unroll
            for (int e = 0; e < NEXP; e++)
                if (e != b1i && acc[e] > b2v) { b2v = acc[e]; b2i = e; }
            float p2 = expf(b2v - b1v);
            float inv = 1.f / (1.f + p2);
            g_e1[warp] = b1i; g_e2[warp] = b2i;
            g_w1[warp] = inv; g_w2[warp] = p2 * inv;
        }
    }
    const int bid = blockIdx.x;                 // 512 blocks
    const int xper = NX4 / 512;
    const int wper = NW4 / 512;
    cvt_slice((const float4*)x,  (uint2*)g_x16, bid * xper, xper, threadIdx.x, 256);
    cvt_slice((const float4*)W1, (uint2*)g_w1h, bid * wper, wper, threadIdx.x, 256);
}

// ---------------- route: counts+prefix+scatter, single block ----------------
__global__ void k_route() {
    __shared__ int cnt[NEXP];
    __shared__ int base[NEXP];
    const int tid = threadIdx.x;                // 1024 threads
    if (tid < NEXP) cnt[tid] = 0;
    __syncthreads();
#pragma unroll
    for (int q = 0; q < 4; q++) {
        int t = tid + q * 1024;
        atomicAdd(&cnt[g_e1[t]], 1);
        atomicAdd(&cnt[g_e2[t]], 1);
    }
    __syncthreads();
    if (tid == 0) {
        int off = 0;
        for (int e = 0; e < NEXP; e++) {
            g_offsets[e] = off;
            base[e] = off;
            off += cnt[e];
        }
        g_offsets[NEXP] = off;
    }
    __syncthreads();
#pragma unroll
    for (int q = 0; q < 4; q++) {
        int t = tid + q * 1024;
        int s1 = atomicAdd(&base[g_e1[t]], 1);
        g_rtok[s1] = t; g_s1[t] = s1;
        int s2 = atomicAdd(&base[g_e2[t]], 1);
        g_rtok[s2] = t; g_s2[t] = s2;
    }
}

// ---------------- fp16 HMMA mainloop: 256 thr, 8 warps (4m x 2n, 64x64), pipelined frags ----------------
// Stage: A [256 m][64 k] swizzled 128B rows (32KB); B [64 k][128 n] swizzled 256B rows (16KB).
template <int NCH>
__device__ __forceinline__ void mma_loop(
    uint32_t sb, const __half* const (&ap)[8], const __half* bsrc, int ldb,
    int tid, float (&acc)[4][8][4])
{
    const int lane = tid & 31, wid = tid >> 5;
    const int wm = (wid >> 1) * 64, wn = (wid & 1) * 64;
    const int g = lane >> 3, r = lane & 7;

    uint32_t adst[8];
#pragma unroll
    for (int j = 0; j < 8; j++)
        adst[j] = SWZ((uint32_t)((tid >> 3) + 32 * j) * 128u + (uint32_t)(tid & 7) * 16u);
    uint32_t bdst[4];
#pragma unroll
    for (int j = 0; j < 4; j++)
        bdst[j] = 32768u + SWZ256((uint32_t)((tid >> 4) + 16 * j) * 256u + (uint32_t)(tid & 15) * 16u);

    // fragment smem addresses (per ks they shift by fixed byte offsets)
    uint32_t a_addr0[4], b_addr0[4];
#pragma unroll
    for (int ms = 0; ms < 4; ms++)
        a_addr0[ms] = (uint32_t)(wm + ms * 16 + (lane & 15)) * 128u + (uint32_t)(lane >> 4) * 16u;
#pragma unroll
    for (int p = 0; p < 4; p++)
        b_addr0[p] = (uint32_t)((g & 1) * 8 + r) * 256u + (uint32_t)(wn + p * 16 + (g >> 1) * 8) * 2u;

#define CPS(ch, s)                                                                    \
    {                                                                                 \
        uint32_t base = sb + (uint32_t)(s) * STAGE_BYTES;                             \
_Pragma("unroll")                                                                     \
        for (int j = 0; j < 8; j++)                                                   \
            cp16(base + adst[j], ap[j] + (size_t)(ch) * 64);                          \
_Pragma("unroll")                                                                     \
        for (int j = 0; j < 4; j++)                                                   \
            cp16(base + bdst[j], bsrc + ((size_t)(ch) * 64 + 16 * j) * ldb);          \
    }
#define LD_FRAGS(As, Bb, ksv, buf)                                                    \
    {                                                                                 \
_Pragma("unroll")                                                                     \
        for (int ms = 0; ms < 4; ms++)                                                \
            ldsm4(af[buf][ms][0], af[buf][ms][1], af[buf][ms][2], af[buf][ms][3],     \
                  (As) + SWZ(a_addr0[ms] + (uint32_t)(ksv) * 32u));                   \
_Pragma("unroll")                                                                     \
        for (int p = 0; p < 4; p++)                                                   \
            ldsm4t(bf[buf][2 * p][0], bf[buf][2 * p][1],                              \
                   bf[buf][2 * p + 1][0], bf[buf][2 * p + 1][1],                      \
                   (Bb) + SWZ256(b_addr0[p] + (uint32_t)(ksv) * 16u * 256u));         \
    }

    uint32_t af[2][4][4], bf[2][8][2];

    CPS(0, 0);
    asm volatile("cp.async.commit_group;" ::: "memory");
    CPS(1, 1);
    asm volatile("cp.async.commit_group;" ::: "memory");

    for (int i = 0; i < NCH; i++) {
        const bool pf = (i + 2) < NCH;
        asm volatile("cp.async.wait_group 1;" ::: "memory");
        __syncthreads();
        if (pf) CPS(i + 2, (i + 2) % 3);
        asm volatile("cp.async.commit_group;" ::: "memory");

        uint32_t As = sb + (uint32_t)(i % 3) * STAGE_BYTES;
        uint32_t Bb = As + 32768u;

        LD_FRAGS(As, Bb, 0, 0);
#pragma unroll
        for (int ks = 0; ks < 4; ks++) {
            const int cur = ks & 1;
            if (ks < 3) LD_FRAGS(As, Bb, ks + 1, cur ^ 1);
#pragma unroll
            for (int ms = 0; ms < 4; ms++)
#pragma unroll
                for (int ns = 0; ns < 8; ns++)
                    mma_f16(acc[ms][ns], af[cur][ms], bf[cur][ns]);
        }
    }
#undef CPS
#undef LD_FRAGS
}

// ---------------- GEMM1 + folded W2 conversion ----------------
__global__ __launch_bounds__(256)
void k_gemm1(const float* __restrict__ b1, const float* __restrict__ W2) {
    // W2 cvt slice (all blocks) — overlaps gemm1 compute across the grid
    {
        const int nb  = 32 * 16 * NEXP;                       // 4096 blocks
        const int bid = blockIdx.x + 32 * (blockIdx.y + 16 * blockIdx.z);
        const int per = NW4 / nb;                             // 2048 float4
        cvt_slice((const float4*)W2, (uint2*)g_w2h, bid * per, per, threadIdx.x, 256);
    }

    const int e  = blockIdx.z;
    const int off = g_offsets[e];
    const int ne  = g_offsets[e + 1] - off;
    const int m0  = blockIdx.y * 256;
    if (m0 >= ne) return;
    const int n0  = blockIdx.x * 128;

    extern __shared__ __align__(1024) char smem[];
    uint32_t sb = smem_u32(smem);
    const int tid = threadIdx.x;

    const __half* ap[8];
#pragma unroll
    for (int j = 0; j < 8; j++) {
        int rr = m0 + (tid >> 3) + 32 * j;
        int tok = g_rtok[off + (rr < ne ? rr : 0)];
        ap[j] = g_x16 + (size_t)tok * CDIM + (tid & 7) * 8;
    }
    const __half* bsrc = g_w1h + (size_t)e * CDIM * HDIM +
                         (size_t)(tid >> 4) * HDIM + n0 + (tid & 15) * 8;

    float acc[4][8][4];
#pragma unroll
    for (int a = 0; a < 4; a++)
#pragma unroll
        for (int b = 0; b < 8; b++)
#pragma unroll
            for (int c = 0; c < 4; c++) acc[a][b][c] = 0.f;

    mma_loop<CDIM / 64>(sb, ap, bsrc, HDIM, tid, acc);

    const int lane = tid & 31, wid = tid >> 5;
    const int grp = lane >> 2, tq = lane & 3;
    const int wm = (wid >> 1) * 64, wn = (wid & 1) * 64;
    const float* brow = b1 + (size_t)e * HDIM + n0 + wn;
#pragma unroll
    for (int ms = 0; ms < 4; ms++)
#pragma unroll
        for (int h = 0; h < 2; h++) {
            int rr = m0 + wm + ms * 16 + grp + h * 8;
            if (rr < ne) {
                __half* hrow = g_h + (size_t)(off + rr) * HDIM + n0 + wn;
#pragma unroll
                for (int ns = 0; ns < 8; ns++) {
                    int col = ns * 8 + 2 * tq;
                    __half2 o = __floats2half2_rn(
                        gelu_exact(acc[ms][ns][h * 2 + 0] + brow[col]),
                        gelu_exact(acc[ms][ns][h * 2 + 1] + brow[col + 1]));
                    *(__half2*)(hrow + col) = o;
                }
            }
        }
}

// ---------------- GEMM2: y = h_slots @ W2h[e] + b2[e] ----------------
__global__ __launch_bounds__(256)
void k_gemm2(const float* __restrict__ b2) {
    const int e  = blockIdx.z;
    const int off = g_offsets[e];
    const int ne  = g_offsets[e + 1] - off;
    const int m0  = blockIdx.y * 256;
    if (m0 >= ne) return;
    const int n0  = blockIdx.x * 128;

    extern __shared__ __align__(1024) char smem[];
    uint32_t sb = smem_u32(smem);
    const int tid = threadIdx.x;

    const __half* ap[8];
#pragma unroll
    for (int j = 0; j < 8; j++) {
        int rr = m0 + (tid >> 3) + 32 * j;
        if (rr >= ne) rr = ne - 1;
        ap[j] = g_h + (size_t)(off + rr) * HDIM + (tid & 7) * 8;
    }
    const __half* bsrc = g_w2h + (size_t)e * HDIM * CDIM +
                         (size_t)(tid >> 4) * CDIM + n0 + (tid & 15) * 8;

    float acc[4][8][4];
#pragma unroll
    for (int a = 0; a < 4; a++)
#pragma unroll
        for (int b = 0; b < 8; b++)
#pragma unroll
            for (int c = 0; c < 4; c++) acc[a][b][c] = 0.f;

    mma_loop<HDIM / 64>(sb, ap, bsrc, CDIM, tid, acc);

    const int lane = tid & 31, wid = tid >> 5;
    const int grp = lane >> 2, tq = lane & 3;
    const int wm = (wid >> 1) * 64, wn = (wid & 1) * 64;
    const float* brow = b2 + (size_t)e * CDIM + n0 + wn;
#pragma unroll
    for (int ms = 0; ms < 4; ms++)
#pragma unroll
        for (int h = 0; h < 2; h++) {
            int rr = m0 + wm + ms * 16 + grp + h * 8;
            if (rr < ne) {
                float* yrow = g_y + (size_t)(off + rr) * CDIM + n0 + wn;
#pragma unroll
                for (int ns = 0; ns < 8; ns++) {
                    int col = ns * 8 + 2 * tq;
                    float2 o;
                    o.x = acc[ms][ns][h * 2 + 0] + brow[col];
                    o.y = acc[ms][ns][h * 2 + 1] + brow[col + 1];
                    *(float2*)(yrow + col) = o;
                }
            }
        }
}

// ---------------- combine: out[t] = w1*y[s1] + w2*y[s2] ----------------
__global__ void k_combine(float* __restrict__ out) {
    int t = blockIdx.x;
    int c = threadIdx.x * 4;
    float w1 = g_w1[t], w2 = g_w2[t];
    const float4 a = *(const float4*)(g_y + (size_t)g_s1[t] * CDIM + c);
    const float4 b = *(const float4*)(g_y + (size_t)g_s2[t] * CDIM + c);
    float4 o;
    o.x = w1 * a.x + w2 * b.x;
    o.y = w1 * a.y + w2 * b.y;
    o.z = w1 * a.z + w2 * b.z;
    o.w = w1 * a.w + w2 * b.w;
    *(float4*)(out + (size_t)t * CDIM + c) = o;
}

extern "C" void kernel_launch(void* const* d_in, const int* in_sizes, int n_in,
                              void* d_out, int out_size) {
    const float* x  = (const float*)d_in[0];
    const float* Wg = (const float*)d_in[1];
    const float* bg = (const float*)d_in[2];
    const float* W1 = (const float*)d_in[3];
    const float* b1 = (const float*)d_in[4];
    const float* W2 = (const float*)d_in[5];
    const float* b2 = (const float*)d_in[6];
    float* out = (float*)d_out;

    cudaFuncSetAttribute(k_gemm1, cudaFuncAttributeMaxDynamicSharedMemorySize, SMEM_BYTES);
    cudaFuncSetAttribute(k_gemm2, cudaFuncAttributeMaxDynamicSharedMemorySize, SMEM_BYTES);

    k_gate<<<512, 256>>>(x, Wg, bg, W1);   // gate + x/W1 cvt
    k_route<<<1, 1024>>>();                // counts + prefix + scatter

    dim3 grd1(HDIM / 128, 16, NEXP);       // worst-case M tiles; W2 cvt folded in
    k_gemm1<<<grd1, 256, SMEM_BYTES>>>(b1, W2);
    dim3 grd2(CDIM / 128, 16, NEXP);
    k_gemm2<<<grd2, 256, SMEM_BYTES>>>(b2);
    k_combine<<<NTOK, 256>>>(out);
}

// round 16
// speedup vs baseline: 1.1467x; 1.1467x over previous
#include <cuda_runtime.h>
#include <cuda_fp16.h>
#include <math.h>
#include <stdint.h>

#define NTOK 4096
#define CDIM 1024
#define HDIM 4096
#define NEXP 8
#define NSLOT (NTOK * 2)

// GEMM geometry: block tile 128(M) x 128(N) x 64(K) fp16, 256 threads = 8 warps (2m x 4n, warp 64x32)
// 3 stages x 32KB = 96KB smem -> 2 CTAs/SM to hide per-chunk barrier bubbles.
#define STAGE_BYTES 32768            // A 16KB + B 16KB
#define SMEM_BYTES  (3 * STAGE_BYTES)

// ---------------- static device scratch ----------------
__device__ int g_offsets[NEXP + 1];
__device__ __align__(16) int g_rtok[NSLOT];
__device__ int g_e1[NTOK], g_e2[NTOK];
__device__ int g_s1[NTOK], g_s2[NTOK];
__device__ float g_w1[NTOK], g_w2[NTOK];
__device__ __align__(256) __half g_x16[(size_t)NTOK * CDIM];          // 8 MiB
__device__ __align__(256) __half g_w1h[(size_t)NEXP * CDIM * HDIM];   // 64 MiB
__device__ __align__(256) __half g_w2h[(size_t)NEXP * HDIM * CDIM];   // 64 MiB
__device__ __align__(256) __half g_h[(size_t)NSLOT * HDIM];           // 64 MiB
__device__ __align__(256) float  g_y[(size_t)NSLOT * CDIM];           // 32 MiB

#define NX4  (NTOK * CDIM / 4)
#define NW4  (NEXP * CDIM * HDIM / 4)

// ---------------- helpers ----------------
__device__ __forceinline__ uint32_t smem_u32(const void* p) {
    uint32_t a;
    asm("{ .reg .u64 t; cvta.to.shared.u64 t, %1; cvt.u32.u64 %0, t; }" : "=r"(a) : "l"(p));
    return a;
}
#define SWZ(o)    ((o) ^ ((((uint32_t)(o)) >> 3) & 0x70u))   // 128B rows
#define SWZ256(o) ((o) ^ ((((uint32_t)(o)) >> 4) & 0x70u))   // 256B rows

__device__ __forceinline__ void cp16(uint32_t dst, const void* src) {
    asm volatile("cp.async.cg.shared.global [%0], [%1], 16;" :: "r"(dst), "l"(src) : "memory");
}
__device__ __forceinline__ void ldsm4(uint32_t& r0, uint32_t& r1, uint32_t& r2, uint32_t& r3, uint32_t a) {
    asm volatile("ldmatrix.sync.aligned.m8n8.x4.shared.b16 {%0,%1,%2,%3}, [%4];"
                 : "=r"(r0), "=r"(r1), "=r"(r2), "=r"(r3) : "r"(a));
}
__device__ __forceinline__ void ldsm4t(uint32_t& r0, uint32_t& r1, uint32_t& r2, uint32_t& r3, uint32_t a) {
    asm volatile("ldmatrix.sync.aligned.m8n8.x4.trans.shared.b16 {%0,%1,%2,%3}, [%4];"
                 : "=r"(r0), "=r"(r1), "=r"(r2), "=r"(r3) : "r"(a));
}
__device__ __forceinline__ void mma_f16(float* c, uint32_t a0, uint32_t a1, uint32_t a2, uint32_t a3,
                                        uint32_t b0, uint32_t b1) {
    asm volatile(
        "mma.sync.aligned.m16n8k16.row.col.f32.f16.f16.f32 "
        "{%0,%1,%2,%3}, {%4,%5,%6,%7}, {%8,%9}, {%0,%1,%2,%3};"
        : "+f"(c[0]), "+f"(c[1]), "+f"(c[2]), "+f"(c[3])
        : "r"(a0), "r"(a1), "r"(a2), "r"(a3), "r"(b0), "r"(b1));
}
__device__ __forceinline__ uint32_t h2u(__half2 h) { return *(uint32_t*)&h; }
__device__ __forceinline__ float gelu_exact(float v) {
    return 0.5f * v * (1.0f + erff(v * 0.70710678118654752f));
}
__device__ __forceinline__ void cvt_slice(const float4* __restrict__ src, uint2* __restrict__ dst,
                                          int start, int count, int tid, int nthr) {
    for (int i = start + tid; i < start + count; i += nthr) {
        float4 v = src[i];
        uint2 o;
        o.x = h2u(__floats2half2_rn(v.x, v.y));
        o.y = h2u(__floats2half2_rn(v.z, v.w));
        dst[i] = o;
    }
}

// ---------------- gate + x/W1 cvt (512 blocks x 256 thr) — R12 proven ----------------
__global__ void k_gate(const float* __restrict__ x, const float* __restrict__ Wg,
                       const float* __restrict__ bg, const float* __restrict__ W1) {
    int warp = (blockIdx.x * blockDim.x + threadIdx.x) >> 5;
    int lane = threadIdx.x & 31;
    if (warp < NTOK) {
        const float* xr = x + (size_t)warp * CDIM;
        float acc[NEXP];
#pragma unroll
        for (int e = 0; e < NEXP; e++) acc[e] = 0.f;
        for (int k = lane; k < CDIM; k += 32) {
            float xv = xr[k];
            const float* wr = Wg + k * NEXP;
#pragma unroll
            for (int e = 0; e < NEXP; e++) acc[e] = fmaf(xv, wr[e], acc[e]);
        }
#pragma unroll
        for (int off = 16; off; off >>= 1)
#pragma unroll
            for (int e = 0; e < NEXP; e++)
                acc[e] += __shfl_xor_sync(0xffffffffu, acc[e], off);
        if (lane == 0) {
#pragma unroll
            for (int e = 0; e < NEXP; e++) acc[e] += bg[e];
            int b1i = 0; float b1v = acc[0];
#pragma unroll
            for (int e = 1; e < NEXP; e++) if (acc[e] > b1v) { b1v = acc[e]; b1i = e; }
            int b2i = -1; float b2v = -3.0e38f;
#pragma unroll
            for (int e = 0; e < NEXP; e++)
                if (e != b1i && acc[e] > b2v) { b2v = acc[e]; b2i = e; }
            float p2 = expf(b2v - b1v);
            float inv = 1.f / (1.f + p2);
            g_e1[warp] = b1i; g_e2[warp] = b2i;
            g_w1[warp] = inv; g_w2[warp] = p2 * inv;
        }
    }
    const int bid = blockIdx.x;                 // 512 blocks
    const int xper = NX4 / 512;
    const int wper = NW4 / 512;
    cvt_slice((const float4*)x,  (uint2*)g_x16, bid * xper, xper, threadIdx.x, 256);
    cvt_slice((const float4*)W1, (uint2*)g_w1h, bid * wper, wper, threadIdx.x, 256);
}

// ---------------- route: counts+prefix+scatter, single block ----------------
__global__ void k_route() {
    __shared__ int cnt[NEXP];
    __shared__ int base[NEXP];
    const int tid = threadIdx.x;                // 1024 threads
    if (tid < NEXP) cnt[tid] = 0;
    __syncthreads();
#pragma unroll
    for (int q = 0; q < 4; q++) {
        int t = tid + q * 1024;
        atomicAdd(&cnt[g_e1[t]], 1);
        atomicAdd(&cnt[g_e2[t]], 1);
    }
    __syncthreads();
    if (tid == 0) {
        int off = 0;
        for (int e = 0; e < NEXP; e++) {
            g_offsets[e] = off;
            base[e] = off;
            off += cnt[e];
        }
        g_offsets[NEXP] = off;
    }
    __syncthreads();
#pragma unroll
    for (int q = 0; q < 4; q++) {
        int t = tid + q * 1024;
        int s1 = atomicAdd(&base[g_e1[t]], 1);
        g_rtok[s1] = t; g_s1[t] = s1;
        int s2 = atomicAdd(&base[g_e2[t]], 1);
        g_rtok[s2] = t; g_s2[t] = s2;
    }
}

// ---------------- fp16 HMMA mainloop (128x128x64, 256 thr, 3-stage cp.async) ----------------
// Stage: A [128 m][64 k] swizzled 128B rows (16KB); B [64 k][128 n] swizzled 256B rows (16KB).
// 8 warps as 2(m) x 4(n): warp tile 64x32; ms 0..3 (m16), ns 0..3 (n8), ks 0..3 (k16).
template <int NCH>
__device__ __forceinline__ void mma_loop(
    uint32_t sb, const __half* const (&ap)[4], const __half* bsrc, int ldb,
    int tid, float (&acc)[4][4][4])
{
    const int lane = tid & 31, wid = tid >> 5;
    const int wm = (wid >> 2) * 64, wn = (wid & 3) * 32;

    uint32_t adst[4];
#pragma unroll
    for (int j = 0; j < 4; j++)
        adst[j] = SWZ((uint32_t)((tid >> 3) + 32 * j) * 128u + (uint32_t)(tid & 7) * 16u);
    uint32_t bdst[4];
#pragma unroll
    for (int j = 0; j < 4; j++)
        bdst[j] = 16384u + SWZ256((uint32_t)((tid >> 4) + 16 * j) * 256u + (uint32_t)(tid & 15) * 16u);

#define CPS(ch, s)                                                                    \
    {                                                                                 \
        uint32_t base = sb + (uint32_t)(s) * STAGE_BYTES;                             \
_Pragma("unroll")                                                                     \
        for (int j = 0; j < 4; j++)                                                   \
            cp16(base + adst[j], ap[j] + (size_t)(ch) * 64);                          \
_Pragma("unroll")                                                                     \
        for (int j = 0; j < 4; j++)                                                   \
            cp16(base + bdst[j], bsrc + ((size_t)(ch) * 64 + 16 * j) * ldb);          \
    }

    CPS(0, 0);
    asm volatile("cp.async.commit_group;" ::: "memory");
    CPS(1, 1);
    asm volatile("cp.async.commit_group;" ::: "memory");

    for (int i = 0; i < NCH; i++) {
        const bool pf = (i + 2) < NCH;
        asm volatile("cp.async.wait_group 1;" ::: "memory");
        __syncthreads();
        if (pf) CPS(i + 2, (i + 2) % 3);
        asm volatile("cp.async.commit_group;" ::: "memory");

        uint32_t As = sb + (uint32_t)(i % 3) * STAGE_BYTES;
        uint32_t Bb = As + 16384u;
#pragma unroll
        for (int ks = 0; ks < 4; ks++) {
            uint32_t bq[4][2];
#pragma unroll
            for (int p = 0; p < 2; p++) {
                int g = lane >> 3, r = lane & 7;
                uint32_t krow = (uint32_t)(ks * 16 + (g & 1) * 8 + r);
                uint32_t nby  = (uint32_t)(wn + p * 16 + (g >> 1) * 8) * 2u;
                uint32_t addr = Bb + SWZ256(krow * 256u + nby);
                ldsm4t(bq[2 * p][0], bq[2 * p][1], bq[2 * p + 1][0], bq[2 * p + 1][1], addr);
            }
#pragma unroll
            for (int ms = 0; ms < 4; ms++) {
                uint32_t row  = (uint32_t)(wm + ms * 16 + (lane & 15));
                uint32_t colb = (uint32_t)(ks * 32 + (lane >> 4) * 16);
                uint32_t addr = As + SWZ(row * 128u + colb);
                uint32_t a0, a1, a2, a3;
                ldsm4(a0, a1, a2, a3, addr);
#pragma unroll
                for (int ns = 0; ns < 4; ns++)
                    mma_f16(acc[ms][ns], a0, a1, a2, a3, bq[ns][0], bq[ns][1]);
            }
        }
    }
#undef CPS
}

// ---------------- GEMM1 + folded W2 conversion ----------------
__global__ __launch_bounds__(256, 2)
void k_gemm1(const float* __restrict__ b1, const float* __restrict__ W2) {
    // W2 cvt slice (all blocks) — overlaps gemm1 compute across the grid
    {
        const int nb  = 32 * 32 * NEXP;                       // 8192 blocks
        const int bid = blockIdx.x + 32 * (blockIdx.y + 32 * blockIdx.z);
        const int per = NW4 / nb;                             // 256 float4
        cvt_slice((const float4*)W2, (uint2*)g_w2h, bid * per, per, threadIdx.x, 256);
    }

    const int e  = blockIdx.z;
    const int off = g_offsets[e];
    const int ne  = g_offsets[e + 1] - off;
    const int m0  = blockIdx.y * 128;
    if (m0 >= ne) return;
    const int n0  = blockIdx.x * 128;

    extern __shared__ __align__(1024) char smem[];
    uint32_t sb = smem_u32(smem);
    const int tid = threadIdx.x;

    const __half* ap[4];
#pragma unroll
    for (int j = 0; j < 4; j++) {
        int rr = m0 + (tid >> 3) + 32 * j;
        int tok = g_rtok[off + (rr < ne ? rr : 0)];
        ap[j] = g_x16 + (size_t)tok * CDIM + (tid & 7) * 8;
    }
    const __half* bsrc = g_w1h + (size_t)e * CDIM * HDIM +
                         (size_t)(tid >> 4) * HDIM + n0 + (tid & 15) * 8;

    float acc[4][4][4];
#pragma unroll
    for (int a = 0; a < 4; a++)
#pragma unroll
        for (int b = 0; b < 4; b++)
#pragma unroll
            for (int c = 0; c < 4; c++) acc[a][b][c] = 0.f;

    mma_loop<CDIM / 64>(sb, ap, bsrc, HDIM, tid, acc);

    const int lane = tid & 31, wid = tid >> 5;
    const int grp = lane >> 2, tq = lane & 3;
    const int wm = (wid >> 2) * 64, wn = (wid & 3) * 32;
    const float* brow = b1 + (size_t)e * HDIM + n0 + wn;
#pragma unroll
    for (int ms = 0; ms < 4; ms++)
#pragma unroll
        for (int h = 0; h < 2; h++) {
            int rr = m0 + wm + ms * 16 + grp + h * 8;
            if (rr < ne) {
                __half* hrow = g_h + (size_t)(off + rr) * HDIM + n0 + wn;
#pragma unroll
                for (int ns = 0; ns < 4; ns++) {
                    int col = ns * 8 + 2 * tq;
                    __half2 o = __floats2half2_rn(
                        gelu_exact(acc[ms][ns][h * 2 + 0] + brow[col]),
                        gelu_exact(acc[ms][ns][h * 2 + 1] + brow[col + 1]));
                    *(__half2*)(hrow + col) = o;
                }
            }
        }
}

// ---------------- GEMM2: y = h_slots @ W2h[e] + b2[e] ----------------
__global__ __launch_bounds__(256, 2)
void k_gemm2(const float* __restrict__ b2) {
    const int e  = blockIdx.z;
    const int off = g_offsets[e];
    const int ne  = g_offsets[e + 1] - off;
    const int m0  = blockIdx.y * 128;
    if (m0 >= ne) return;
    const int n0  = blockIdx.x * 128;

    extern __shared__ __align__(1024) char smem[];
    uint32_t sb = smem_u32(smem);
    const int tid = threadIdx.x;

    const __half* ap[4];
#pragma unroll
    for (int j = 0; j < 4; j++) {
        int rr = m0 + (tid >> 3) + 32 * j;
        if (rr >= ne) rr = ne - 1;
        ap[j] = g_h + (size_t)(off + rr) * HDIM + (tid & 7) * 8;
    }
    const __half* bsrc = g_w2h + (size_t)e * HDIM * CDIM +
                         (size_t)(tid >> 4) * CDIM + n0 + (tid & 15) * 8;

    float acc[4][4][4];
#pragma unroll
    for (int a = 0; a < 4; a++)
#pragma unroll
        for (int b = 0; b < 4; b++)
#pragma unroll
            for (int c = 0; c < 4; c++) acc[a][b][c] = 0.f;

    mma_loop<HDIM / 64>(sb, ap, bsrc, CDIM, tid, acc);

    const int lane = tid & 31, wid = tid >> 5;
    const int grp = lane >> 2, tq = lane & 3;
    const int wm = (wid >> 2) * 64, wn = (wid & 3) * 32;
    const float* brow = b2 + (size_t)e * CDIM + n0 + wn;
#pragma unroll
    for (int ms = 0; ms < 4; ms++)
#pragma unroll
        for (int h = 0; h < 2; h++) {
            int rr = m0 + wm + ms * 16 + grp + h * 8;
            if (rr < ne) {
                float* yrow = g_y + (size_t)(off + rr) * CDIM + n0 + wn;
#pragma unroll
                for (int ns = 0; ns < 4; ns++) {
                    int col = ns * 8 + 2 * tq;
                    float2 o;
                    o.x = acc[ms][ns][h * 2 + 0] + brow[col];
                    o.y = acc[ms][ns][h * 2 + 1] + brow[col + 1];
                    *(float2*)(yrow + col) = o;
                }
            }
        }
}

// ---------------- combine: out[t] = w1*y[s1] + w2*y[s2] ----------------
__global__ void k_combine(float* __restrict__ out) {
    int t = blockIdx.x;
    int c = threadIdx.x * 4;
    float w1 = g_w1[t], w2 = g_w2[t];
    const float4 a = *(const float4*)(g_y + (size_t)g_s1[t] * CDIM + c);
    const float4 b = *(const float4*)(g_y + (size_t)g_s2[t] * CDIM + c);
    float4 o;
    o.x = w1 * a.x + w2 * b.x;
    o.y = w1 * a.y + w2 * b.y;
    o.z = w1 * a.z + w2 * b.z;
    o.w = w1 * a.w + w2 * b.w;
    *(float4*)(out + (size_t)t * CDIM + c) = o;
}

extern "C" void kernel_launch(void* const* d_in, const int* in_sizes, int n_in,
                              void* d_out, int out_size) {
    const float* x  = (const float*)d_in[0];
    const float* Wg = (const float*)d_in[1];
    const float* bg = (const float*)d_in[2];
    const float* W1 = (const float*)d_in[3];
    const float* b1 = (const float*)d_in[4];
    const float* W2 = (const float*)d_in[5];
    const float* b2 = (const float*)d_in[6];
    float* out = (float*)d_out;

    cudaFuncSetAttribute(k_gemm1, cudaFuncAttributeMaxDynamicSharedMemorySize, SMEM_BYTES);
    cudaFuncSetAttribute(k_gemm2, cudaFuncAttributeMaxDynamicSharedMemorySize, SMEM_BYTES);

    k_gate<<<512, 256>>>(x, Wg, bg, W1);   // gate + x/W1 cvt
    k_route<<<1, 1024>>>();                // counts + prefix + scatter

    dim3 grd1(HDIM / 128, 32, NEXP);       // 128-row M tiles; W2 cvt folded in
    k_gemm1<<<grd1, 256, SMEM_BYTES>>>(b1, W2);
    dim3 grd2(CDIM / 128, 32, NEXP);
    k_gemm2<<<grd2, 256, SMEM_BYTES>>>(b2);
    k_combine<<<NTOK, 256>>>(out);
}